// round 2
// baseline (speedup 1.0000x reference)
#include <cuda_runtime.h>

#define NN 100000
#define EE 1600000
#define D 64
#define EPSF 1e-9f

// ---- static device scratch (no allocation allowed) ----
__device__ float g_h[NN * D];
__device__ float g_A1[NN * D];
__device__ float g_A2[NN * D];
__device__ float g_A3[NN * D];
__device__ float g_Suh[NN * D];   // sum_{s in N(d)} u[s]*h[s]
__device__ float g_SuA1[NN * D];  // sum_{s in N(d)} u[s]*A1[s]
__device__ int   g_deg[NN];
__device__ int   g_offs[NN];
__device__ int   g_cursor[NN];
__device__ int   g_blockSums[1024];
__device__ float g_u[NN];
__device__ float g_Su[NN];
__device__ float g_Su2[NN];
__device__ int   g_csr[EE];

// ---------------- zero ----------------
__global__ void k_zero() {
    int i = blockIdx.x * blockDim.x + threadIdx.x;
    if (i < NN) { g_deg[i] = 0; g_cursor[i] = 0; }
}

// ---------------- degree ----------------
__global__ void k_deg(const int* __restrict__ src) {
    int e = blockIdx.x * blockDim.x + threadIdx.x;
    if (e < EE) atomicAdd(&g_deg[src[e]], 1);
}

// ---------------- h = x @ W + b ----------------
__global__ void k_gemm(const float* __restrict__ x, const float* __restrict__ W,
                       const float* __restrict__ b) {
    __shared__ float Ws[D * D];
    __shared__ float bs[D];
    for (int i = threadIdx.x; i < D * D; i += blockDim.x) Ws[i] = W[i];
    if (threadIdx.x < D) bs[threadIdx.x] = b[threadIdx.x];
    __syncthreads();
    int row = blockIdx.x * blockDim.x + threadIdx.x;
    if (row >= NN) return;
    float acc[D];
#pragma unroll
    for (int j = 0; j < D; j++) acc[j] = bs[j];
    const float4* xr = (const float4*)(x + (size_t)row * D);
#pragma unroll 2
    for (int k4 = 0; k4 < 16; k4++) {
        float4 xv = xr[k4];
#pragma unroll
        for (int kk = 0; kk < 4; kk++) {
            float xk = (kk == 0) ? xv.x : (kk == 1) ? xv.y : (kk == 2) ? xv.z : xv.w;
            const float4* wr = (const float4*)&Ws[(k4 * 4 + kk) * D];
#pragma unroll
            for (int j4 = 0; j4 < 16; j4++) {
                float4 w = wr[j4];
                acc[j4 * 4 + 0] += xk * w.x;
                acc[j4 * 4 + 1] += xk * w.y;
                acc[j4 * 4 + 2] += xk * w.z;
                acc[j4 * 4 + 3] += xk * w.w;
            }
        }
    }
    float4* hr = (float4*)(g_h + (size_t)row * D);
#pragma unroll
    for (int j4 = 0; j4 < 16; j4++)
        hr[j4] = make_float4(acc[j4 * 4], acc[j4 * 4 + 1], acc[j4 * 4 + 2], acc[j4 * 4 + 3]);
}

// ---------------- per-node u ----------------
__global__ void k_u(const float* __restrict__ lm) {
    int i = blockIdx.x * blockDim.x + threadIdx.x;
    if (i >= NN) return;
    int dg = g_deg[i];
    g_u[i] = (dg <= 1) ? 0.f : lm[0] / ((float)dg - 1.0f + EPSF);
}

// ---------------- exclusive prefix sum of deg -> offs ----------------
__global__ void k_scan1() {  // 1024 threads per block, chunk of 1024
    __shared__ int s[1024];
    int t = threadIdx.x;
    int i = blockIdx.x * 1024 + t;
    int v = (i < NN) ? g_deg[i] : 0;
    s[t] = v;
    __syncthreads();
    for (int off = 1; off < 1024; off <<= 1) {
        int add = (t >= off) ? s[t - off] : 0;
        __syncthreads();
        s[t] += add;
        __syncthreads();
    }
    if (i < NN) g_offs[i] = s[t] - v;  // exclusive
    if (t == 1023) g_blockSums[blockIdx.x] = s[t];
}

__global__ void k_scan2(int nb) {
    if (blockIdx.x == 0 && threadIdx.x == 0) {
        int run = 0;
        for (int i = 0; i < nb; i++) { int v = g_blockSums[i]; g_blockSums[i] = run; run += v; }
    }
}

__global__ void k_scan3() {
    int i = blockIdx.x * blockDim.x + threadIdx.x;
    if (i < NN) g_offs[i] += g_blockSums[i >> 10];
}

// ---------------- CSR fill (group edges by dst, store src) ----------------
__global__ void k_fill(const int* __restrict__ src, const int* __restrict__ dst) {
    int e = blockIdx.x * blockDim.x + threadIdx.x;
    if (e >= EE) return;
    int d = dst[e];
    int pos = atomicAdd(&g_cursor[d], 1);
    g_csr[g_offs[d] + pos] = src[e];
}

// ---------------- per-node sort (determinism + locality) ----------------
__global__ void k_sort() {
    int n = blockIdx.x * blockDim.x + threadIdx.x;
    if (n >= NN) return;
    int st = g_offs[n], dg = g_deg[n];
    for (int i = 1; i < dg; i++) {
        int key = g_csr[st + i];
        int j = i - 1;
        while (j >= 0 && g_csr[st + j] > key) { g_csr[st + j + 1] = g_csr[st + j]; j--; }
        g_csr[st + j + 1] = key;
    }
}

// ---------------- aggregation passes: warp per node, 2 floats/lane ----------------
__global__ void k_pass1(const float* __restrict__ lm) {
    int wid = (blockIdx.x * blockDim.x + threadIdx.x) >> 5;
    int lane = threadIdx.x & 31;
    if (wid >= NN) return;
    int st = g_offs[wid], dg = g_deg[wid];
    float2 m0 = make_float2(0.f, 0.f), suh = make_float2(0.f, 0.f);
    float suL = 0.f, su2L = 0.f;
    for (int base = 0; base < dg; base += 32) {
        int cnt = min(32, dg - base);
        int sIdx = 0; float uL = 0.f;
        if (lane < cnt) { sIdx = g_csr[st + base + lane]; uL = g_u[sIdx]; }
        suL += uL; su2L += uL * uL;
        for (int i = 0; i < cnt; i++) {
            int s = __shfl_sync(0xffffffffu, sIdx, i);
            float us = __shfl_sync(0xffffffffu, uL, i);
            float2 v = *(const float2*)(g_h + (size_t)s * D + lane * 2);
            m0.x += v.x; m0.y += v.y;
            suh.x += us * v.x; suh.y += us * v.y;
        }
    }
    for (int o = 16; o > 0; o >>= 1) {
        suL += __shfl_xor_sync(0xffffffffu, suL, o);
        su2L += __shfl_xor_sync(0xffffffffu, su2L, o);
    }
    float lam = lm[0];
    float ud = g_u[wid];
    float2 hd = *(const float2*)(g_h + (size_t)wid * D + lane * 2);
    float2 a1;
    if (dg == 1) a1 = hd;
    else { a1.x = (1.f - lam) * hd.x + ud * m0.x; a1.y = (1.f - lam) * hd.y + ud * m0.y; }
    *(float2*)(g_A1 + (size_t)wid * D + lane * 2) = a1;
    *(float2*)(g_Suh + (size_t)wid * D + lane * 2) = suh;
    if (lane == 0) { g_Su[wid] = suL; g_Su2[wid] = su2L; }
}

__global__ void k_pass2(const float* __restrict__ lm) {
    int wid = (blockIdx.x * blockDim.x + threadIdx.x) >> 5;
    int lane = threadIdx.x & 31;
    if (wid >= NN) return;
    int st = g_offs[wid], dg = g_deg[wid];
    float2 sa1 = make_float2(0.f, 0.f), sua1 = make_float2(0.f, 0.f);
    for (int base = 0; base < dg; base += 32) {
        int cnt = min(32, dg - base);
        int sIdx = 0; float uL = 0.f;
        if (lane < cnt) { sIdx = g_csr[st + base + lane]; uL = g_u[sIdx]; }
        for (int i = 0; i < cnt; i++) {
            int s = __shfl_sync(0xffffffffu, sIdx, i);
            float us = __shfl_sync(0xffffffffu, uL, i);
            float2 v = *(const float2*)(g_A1 + (size_t)s * D + lane * 2);
            sa1.x += v.x; sa1.y += v.y;
            sua1.x += us * v.x; sua1.y += us * v.y;
        }
    }
    float lam = lm[0];
    float su = g_Su[wid];
    float ud = g_u[wid];
    float2 hd = *(const float2*)(g_h + (size_t)wid * D + lane * 2);
    float2 m1, a2;
    m1.x = sa1.x - su * hd.x; m1.y = sa1.y - su * hd.y;
    if (dg == 1) a2 = hd;
    else { a2.x = (1.f - lam) * hd.x + ud * m1.x; a2.y = (1.f - lam) * hd.y + ud * m1.y; }
    *(float2*)(g_A2 + (size_t)wid * D + lane * 2) = a2;
    *(float2*)(g_SuA1 + (size_t)wid * D + lane * 2) = sua1;
}

__global__ void k_pass3(const float* __restrict__ lm) {
    int wid = (blockIdx.x * blockDim.x + threadIdx.x) >> 5;
    int lane = threadIdx.x & 31;
    if (wid >= NN) return;
    int st = g_offs[wid], dg = g_deg[wid];
    float2 sa2 = make_float2(0.f, 0.f);
    for (int base = 0; base < dg; base += 32) {
        int cnt = min(32, dg - base);
        int sIdx = 0;
        if (lane < cnt) sIdx = g_csr[st + base + lane];
        for (int i = 0; i < cnt; i++) {
            int s = __shfl_sync(0xffffffffu, sIdx, i);
            float2 v = *(const float2*)(g_A2 + (size_t)s * D + lane * 2);
            sa2.x += v.x; sa2.y += v.y;
        }
    }
    float lam = lm[0];
    float su = g_Su[wid];
    float ud = g_u[wid];
    float2 hd = *(const float2*)(g_h + (size_t)wid * D + lane * 2);
    float2 a1d = *(const float2*)(g_A1 + (size_t)wid * D + lane * 2);
    float2 suhd = *(const float2*)(g_Suh + (size_t)wid * D + lane * 2);
    float2 m2, a3;
    m2.x = sa2.x - su * a1d.x + ud * suhd.x;
    m2.y = sa2.y - su * a1d.y + ud * suhd.y;
    if (dg == 1) a3 = hd;
    else { a3.x = (1.f - lam) * hd.x + ud * m2.x; a3.y = (1.f - lam) * hd.y + ud * m2.y; }
    *(float2*)(g_A3 + (size_t)wid * D + lane * 2) = a3;
}

__global__ void k_pass4(const float* __restrict__ lm, const float* __restrict__ x,
                        float* __restrict__ out) {
    int wid = (blockIdx.x * blockDim.x + threadIdx.x) >> 5;
    int lane = threadIdx.x & 31;
    if (wid >= NN) return;
    int st = g_offs[wid], dg = g_deg[wid];
    float2 sa3 = make_float2(0.f, 0.f);
    for (int base = 0; base < dg; base += 32) {
        int cnt = min(32, dg - base);
        int sIdx = 0;
        if (lane < cnt) sIdx = g_csr[st + base + lane];
        for (int i = 0; i < cnt; i++) {
            int s = __shfl_sync(0xffffffffu, sIdx, i);
            float2 v = *(const float2*)(g_A3 + (size_t)s * D + lane * 2);
            sa3.x += v.x; sa3.y += v.y;
        }
    }
    float lam = lm[0];
    float su = g_Su[wid];
    float su2 = g_Su2[wid];
    float ud = g_u[wid];
    float2 hd = *(const float2*)(g_h + (size_t)wid * D + lane * 2);
    float2 a2d = *(const float2*)(g_A2 + (size_t)wid * D + lane * 2);
    float2 sua1d = *(const float2*)(g_SuA1 + (size_t)wid * D + lane * 2);
    float2 xd = *(const float2*)(x + (size_t)wid * D + lane * 2);
    float2 m3, tmp;
    m3.x = sa3.x - su * a2d.x + ud * sua1d.x - ud * su2 * hd.x;
    m3.y = sa3.y - su * a2d.y + ud * sua1d.y - ud * su2 * hd.y;
    if (dg == 0) { tmp = hd; }
    else {
        float c = lam / ((float)dg + EPSF);
        tmp.x = (1.f - lam) * hd.x + c * m3.x;
        tmp.y = (1.f - lam) * hd.y + c * m3.y;
    }
    float2 o;
    o.x = xd.x + fmaxf(tmp.x, 0.f);
    o.y = xd.y + fmaxf(tmp.y, 0.f);
    *(float2*)(out + (size_t)wid * D + lane * 2) = o;
}

extern "C" void kernel_launch(void* const* d_in, const int* in_sizes, int n_in,
                              void* d_out, int out_size) {
    const float* x = (const float*)d_in[0];
    const int* edge_index = (const int*)d_in[1];
    const float* W = (const float*)d_in[2];
    const float* b = (const float*)d_in[3];
    const float* lm = (const float*)d_in[4];
    float* out = (float*)d_out;

    const int* src = edge_index;        // row 0
    const int* dst = edge_index + EE;   // row 1

    k_zero<<<(NN + 255) / 256, 256>>>();
    k_deg<<<(EE + 255) / 256, 256>>>(src);
    k_gemm<<<(NN + 127) / 128, 128>>>(x, W, b);
    k_u<<<(NN + 255) / 256, 256>>>(lm);

    int nb = (NN + 1023) / 1024;
    k_scan1<<<nb, 1024>>>();
    k_scan2<<<1, 32>>>(nb);
    k_scan3<<<(NN + 255) / 256, 256>>>();
    k_fill<<<(EE + 255) / 256, 256>>>(src, dst);
    k_sort<<<(NN + 255) / 256, 256>>>();

    int blocks = (NN * 32 + 255) / 256;  // warp per node
    k_pass1<<<blocks, 256>>>(lm);
    k_pass2<<<blocks, 256>>>(lm);
    k_pass3<<<blocks, 256>>>(lm);
    k_pass4<<<blocks, 256>>>(lm, x, out);
}

// round 3
// speedup vs baseline: 1.2903x; 1.2903x over previous
#include <cuda_runtime.h>

#define NN 100000
#define EE 1600000
#define D 64
#define MAXD 96
#define EPSF 1e-9f

// ---- static device scratch (no allocation allowed) ----
__device__ float g_h[NN * D];
__device__ float g_A1[NN * D];
__device__ float g_A2[NN * D];
__device__ float g_A3[NN * D];
__device__ float g_Suh[NN * D];   // sum_{s in N(d)} u[s]*h[s]
__device__ float g_SuA1[NN * D];  // sum_{s in N(d)} u[s]*A1[s]
__device__ int   g_deg[NN];
__device__ int   g_cursor[NN];
__device__ float g_u[NN];
__device__ float g_Su[NN];
__device__ float g_Su2[NN];
__device__ int   g_csr[(size_t)NN * MAXD];

// ---------------- h = x @ W + b  (also zeroes cursor) ----------------
__global__ void k_gemm(const float* __restrict__ x, const float* __restrict__ W,
                       const float* __restrict__ b) {
    __shared__ float Ws[D * D];
    __shared__ float bs[D];
    for (int i = threadIdx.x; i < D * D; i += blockDim.x) Ws[i] = W[i];
    if (threadIdx.x < D) bs[threadIdx.x] = b[threadIdx.x];
    __syncthreads();
    int row = blockIdx.x * blockDim.x + threadIdx.x;
    if (row >= NN) return;
    g_cursor[row] = 0;
    float acc[D];
#pragma unroll
    for (int j = 0; j < D; j++) acc[j] = bs[j];
    const float4* xr = (const float4*)(x + (size_t)row * D);
#pragma unroll 2
    for (int k4 = 0; k4 < 16; k4++) {
        float4 xv = xr[k4];
#pragma unroll
        for (int kk = 0; kk < 4; kk++) {
            float xk = (kk == 0) ? xv.x : (kk == 1) ? xv.y : (kk == 2) ? xv.z : xv.w;
            const float4* wr = (const float4*)&Ws[(k4 * 4 + kk) * D];
#pragma unroll
            for (int j4 = 0; j4 < 16; j4++) {
                float4 w = wr[j4];
                acc[j4 * 4 + 0] += xk * w.x;
                acc[j4 * 4 + 1] += xk * w.y;
                acc[j4 * 4 + 2] += xk * w.z;
                acc[j4 * 4 + 3] += xk * w.w;
            }
        }
    }
    float4* hr = (float4*)(g_h + (size_t)row * D);
#pragma unroll
    for (int j4 = 0; j4 < 16; j4++)
        hr[j4] = make_float4(acc[j4 * 4], acc[j4 * 4 + 1], acc[j4 * 4 + 2], acc[j4 * 4 + 3]);
}

// ---------------- CSR fill (fixed stride; cursor doubles as degree) ----------------
__global__ void k_fill(const int* __restrict__ src, const int* __restrict__ dst) {
    int e = blockIdx.x * blockDim.x + threadIdx.x;
    if (e >= EE) return;
    int d = dst[e];
    int pos = atomicAdd(&g_cursor[d], 1);
    if (pos < MAXD) g_csr[(size_t)d * MAXD + pos] = src[e];
}

// ---------------- warp-per-node smem odd-even sort + u/deg ----------------
__global__ void k_sortu(const float* __restrict__ lm) {
    __shared__ int sbuf[8][MAXD];
    int w = threadIdx.x >> 5;
    int lane = threadIdx.x & 31;
    int n = (blockIdx.x * blockDim.x + threadIdx.x) >> 5;
    if (n >= NN) return;
    int dgRaw = g_cursor[n];
    int dg = min(dgRaw, MAXD);
    int* buf = sbuf[w];
    const size_t base = (size_t)n * MAXD;
    for (int i = lane; i < dg; i += 32) buf[i] = g_csr[base + i];
    __syncwarp();
    for (int it = 0; it < dg; ++it) {
        int p = it & 1;
        for (int k = lane;; k += 32) {
            int j = p + 2 * k;
            if (j + 1 >= dg) break;
            int a = buf[j], bb = buf[j + 1];
            if (a > bb) { buf[j] = bb; buf[j + 1] = a; }
        }
        __syncwarp();
    }
    for (int i = lane; i < dg; i += 32) g_csr[base + i] = buf[i];
    if (lane == 0) {
        g_deg[n] = dg;
        g_u[n] = (dg <= 1) ? 0.f : lm[0] / ((float)dg - 1.0f + EPSF);
    }
}

// ---------------- aggregation passes: warp per node, smem-staged indices ----------------
__global__ void k_pass1(const float* __restrict__ lm) {
    __shared__ int sI[8][MAXD];
    __shared__ float sU[8][MAXD];
    int w = threadIdx.x >> 5;
    int lane = threadIdx.x & 31;
    int n = (blockIdx.x * blockDim.x + threadIdx.x) >> 5;
    if (n >= NN) return;
    int dg = g_deg[n];
    const size_t base = (size_t)n * MAXD;
    float suL = 0.f, su2L = 0.f;
    for (int i = lane; i < dg; i += 32) {
        int s = g_csr[base + i];
        float us = __ldg(&g_u[s]);
        sI[w][i] = s; sU[w][i] = us;
        suL += us; su2L += us * us;
    }
    __syncwarp();
    float2 m0 = make_float2(0.f, 0.f), suh = make_float2(0.f, 0.f);
#pragma unroll 4
    for (int i = 0; i < dg; i++) {
        int s = sI[w][i];
        float us = sU[w][i];
        float2 v = __ldg((const float2*)(g_h + (size_t)s * D + lane * 2));
        m0.x += v.x; m0.y += v.y;
        suh.x += us * v.x; suh.y += us * v.y;
    }
    for (int o = 16; o > 0; o >>= 1) {
        suL += __shfl_xor_sync(0xffffffffu, suL, o);
        su2L += __shfl_xor_sync(0xffffffffu, su2L, o);
    }
    float lam = lm[0];
    float ud = g_u[n];
    float2 hd = *(const float2*)(g_h + (size_t)n * D + lane * 2);
    float2 a1;
    if (dg == 1) a1 = hd;
    else { a1.x = (1.f - lam) * hd.x + ud * m0.x; a1.y = (1.f - lam) * hd.y + ud * m0.y; }
    *(float2*)(g_A1 + (size_t)n * D + lane * 2) = a1;
    *(float2*)(g_Suh + (size_t)n * D + lane * 2) = suh;
    if (lane == 0) { g_Su[n] = suL; g_Su2[n] = su2L; }
}

__global__ void k_pass2(const float* __restrict__ lm) {
    __shared__ int sI[8][MAXD];
    __shared__ float sU[8][MAXD];
    int w = threadIdx.x >> 5;
    int lane = threadIdx.x & 31;
    int n = (blockIdx.x * blockDim.x + threadIdx.x) >> 5;
    if (n >= NN) return;
    int dg = g_deg[n];
    const size_t base = (size_t)n * MAXD;
    for (int i = lane; i < dg; i += 32) {
        int s = g_csr[base + i];
        sI[w][i] = s; sU[w][i] = __ldg(&g_u[s]);
    }
    __syncwarp();
    float2 sa1 = make_float2(0.f, 0.f), sua1 = make_float2(0.f, 0.f);
#pragma unroll 4
    for (int i = 0; i < dg; i++) {
        int s = sI[w][i];
        float us = sU[w][i];
        float2 v = __ldg((const float2*)(g_A1 + (size_t)s * D + lane * 2));
        sa1.x += v.x; sa1.y += v.y;
        sua1.x += us * v.x; sua1.y += us * v.y;
    }
    float lam = lm[0];
    float su = g_Su[n];
    float ud = g_u[n];
    float2 hd = *(const float2*)(g_h + (size_t)n * D + lane * 2);
    float2 m1, a2;
    m1.x = sa1.x - su * hd.x; m1.y = sa1.y - su * hd.y;
    if (dg == 1) a2 = hd;
    else { a2.x = (1.f - lam) * hd.x + ud * m1.x; a2.y = (1.f - lam) * hd.y + ud * m1.y; }
    *(float2*)(g_A2 + (size_t)n * D + lane * 2) = a2;
    *(float2*)(g_SuA1 + (size_t)n * D + lane * 2) = sua1;
}

__global__ void k_pass3(const float* __restrict__ lm) {
    __shared__ int sI[8][MAXD];
    int w = threadIdx.x >> 5;
    int lane = threadIdx.x & 31;
    int n = (blockIdx.x * blockDim.x + threadIdx.x) >> 5;
    if (n >= NN) return;
    int dg = g_deg[n];
    const size_t base = (size_t)n * MAXD;
    for (int i = lane; i < dg; i += 32) sI[w][i] = g_csr[base + i];
    __syncwarp();
    float2 sa2 = make_float2(0.f, 0.f);
#pragma unroll 4
    for (int i = 0; i < dg; i++) {
        int s = sI[w][i];
        float2 v = __ldg((const float2*)(g_A2 + (size_t)s * D + lane * 2));
        sa2.x += v.x; sa2.y += v.y;
    }
    float lam = lm[0];
    float su = g_Su[n];
    float ud = g_u[n];
    float2 hd = *(const float2*)(g_h + (size_t)n * D + lane * 2);
    float2 a1d = *(const float2*)(g_A1 + (size_t)n * D + lane * 2);
    float2 suhd = *(const float2*)(g_Suh + (size_t)n * D + lane * 2);
    float2 m2, a3;
    m2.x = sa2.x - su * a1d.x + ud * suhd.x;
    m2.y = sa2.y - su * a1d.y + ud * suhd.y;
    if (dg == 1) a3 = hd;
    else { a3.x = (1.f - lam) * hd.x + ud * m2.x; a3.y = (1.f - lam) * hd.y + ud * m2.y; }
    *(float2*)(g_A3 + (size_t)n * D + lane * 2) = a3;
}

__global__ void k_pass4(const float* __restrict__ lm, const float* __restrict__ x,
                        float* __restrict__ out) {
    __shared__ int sI[8][MAXD];
    int w = threadIdx.x >> 5;
    int lane = threadIdx.x & 31;
    int n = (blockIdx.x * blockDim.x + threadIdx.x) >> 5;
    if (n >= NN) return;
    int dg = g_deg[n];
    const size_t base = (size_t)n * MAXD;
    for (int i = lane; i < dg; i += 32) sI[w][i] = g_csr[base + i];
    __syncwarp();
    float2 sa3 = make_float2(0.f, 0.f);
#pragma unroll 4
    for (int i = 0; i < dg; i++) {
        int s = sI[w][i];
        float2 v = __ldg((const float2*)(g_A3 + (size_t)s * D + lane * 2));
        sa3.x += v.x; sa3.y += v.y;
    }
    float lam = lm[0];
    float su = g_Su[n];
    float su2 = g_Su2[n];
    float ud = g_u[n];
    float2 hd = *(const float2*)(g_h + (size_t)n * D + lane * 2);
    float2 a2d = *(const float2*)(g_A2 + (size_t)n * D + lane * 2);
    float2 sua1d = *(const float2*)(g_SuA1 + (size_t)n * D + lane * 2);
    float2 xd = *(const float2*)(x + (size_t)n * D + lane * 2);
    float2 m3, tmp;
    m3.x = sa3.x - su * a2d.x + ud * sua1d.x - ud * su2 * hd.x;
    m3.y = sa3.y - su * a2d.y + ud * sua1d.y - ud * su2 * hd.y;
    if (dg == 0) { tmp = hd; }
    else {
        float c = lam / ((float)dg + EPSF);
        tmp.x = (1.f - lam) * hd.x + c * m3.x;
        tmp.y = (1.f - lam) * hd.y + c * m3.y;
    }
    float2 o;
    o.x = xd.x + fmaxf(tmp.x, 0.f);
    o.y = xd.y + fmaxf(tmp.y, 0.f);
    *(float2*)(out + (size_t)n * D + lane * 2) = o;
}

extern "C" void kernel_launch(void* const* d_in, const int* in_sizes, int n_in,
                              void* d_out, int out_size) {
    const float* x = (const float*)d_in[0];
    const int* edge_index = (const int*)d_in[1];
    const float* W = (const float*)d_in[2];
    const float* b = (const float*)d_in[3];
    const float* lm = (const float*)d_in[4];
    float* out = (float*)d_out;

    const int* src = edge_index;        // row 0
    const int* dst = edge_index + EE;   // row 1

    k_gemm<<<(NN + 127) / 128, 128>>>(x, W, b);          // also zeroes cursor
    k_fill<<<(EE + 255) / 256, 256>>>(src, dst);         // cursor becomes degree
    int wblocks = (NN * 32 + 255) / 256;                 // warp per node
    k_sortu<<<wblocks, 256>>>(lm);                       // sort + u + deg
    k_pass1<<<wblocks, 256>>>(lm);
    k_pass2<<<wblocks, 256>>>(lm);
    k_pass3<<<wblocks, 256>>>(lm);
    k_pass4<<<wblocks, 256>>>(lm, x, out);
}